// round 14
// baseline (speedup 1.0000x reference)
#include <cuda_runtime.h>
#include <math.h>
#include <stdint.h>

// ---------------------------------------------------------------------------
// MHA: x[2,2048,1024], 16 heads x 64, causal, fp32 I/O.
// R14: GEMM -> 3-stage cp.async ring, ONE barrier per chunk (latency fully
//      hidden, barrier count halved). Flash -> single barrier per key tile
//      on the 2-buffer ring. Numerics identical to R13.
// ---------------------------------------------------------------------------
#define BATCH   2
#define SEQ     2048
#define DMODEL  1024
#define NHEAD   16
#define HDIM    64
#define MTOT    (BATCH * SEQ)          // 4096 rows

__device__ float g_q[MTOT * DMODEL];
__device__ float g_k[MTOT * DMODEL];
__device__ float g_v[MTOT * DMODEL];
__device__ float g_ctx[MTOT * DMODEL];
__device__ float g_xr[MTOT * DMODEL];        // tf32-rounded x
__device__ float g_wT[4][DMODEL * DMODEL];   // transposed + rounded weights

__device__ __forceinline__ float to_tf32(float x) {
    uint32_t i = __float_as_uint(x), o;
    asm("cvt.rna.tf32.f32 %0, %1;" : "=r"(o) : "r"(i));
    return __uint_as_float(o);
}
__device__ __forceinline__ float ex2f(float x) {
    float y;
    asm("ex2.approx.ftz.f32 %0, %1;" : "=f"(y) : "f"(x));
    return y;
}

#define MMA_TF32(c0, c1, c2, c3, a0, a1, a2, a3, b0, b1)                     \
    asm volatile("mma.sync.aligned.m16n8k8.row.col.f32.tf32.tf32.f32 "       \
                 "{%0,%1,%2,%3}, {%4,%5,%6,%7}, {%8,%9}, {%0,%1,%2,%3};"     \
                 : "+f"(c0), "+f"(c1), "+f"(c2), "+f"(c3)                    \
                 : "r"(a0), "r"(a1), "r"(a2), "r"(a3), "r"(b0), "r"(b1))

__device__ __forceinline__ void cp16(float* dst, const float* src) {
    uint32_t d = (uint32_t)__cvta_generic_to_shared(dst);
    asm volatile("cp.async.ca.shared.global [%0], [%1], 16;" :: "r"(d), "l"(src));
}
#define CP_COMMIT()  asm volatile("cp.async.commit_group;" ::: "memory")
#define CP_WAIT(n)   asm volatile("cp.async.wait_group %0;" :: "n"(n) : "memory")

// ---------------------------------------------------------------------------
// Elementwise tf32 round (for x)
// ---------------------------------------------------------------------------
__global__ void __launch_bounds__(256)
round_kernel(const float* __restrict__ src, float* __restrict__ dst)
{
    int i = (blockIdx.x * 256 + threadIdx.x);
    float4 v = *(const float4*)(src + (size_t)i * 4);
    v.x = to_tf32(v.x); v.y = to_tf32(v.y);
    v.z = to_tf32(v.z); v.w = to_tf32(v.w);
    *(float4*)(dst + (size_t)i * 4) = v;
}

// ---------------------------------------------------------------------------
// Fused weight transpose + tf32 round: 4 weights in one launch (grid.z = 4).
// ---------------------------------------------------------------------------
__global__ void __launch_bounds__(256)
transpose_round4_kernel(const float* __restrict__ S0, const float* __restrict__ S1,
                        const float* __restrict__ S2, const float* __restrict__ S3,
                        float* __restrict__ D)
{
    __shared__ float t[32][33];
    const int z = blockIdx.z;
    const float* S = (z == 0) ? S0 : (z == 1) ? S1 : (z == 2) ? S2 : S3;
    float* Dz = D + (size_t)z * DMODEL * DMODEL;
    const int bx = blockIdx.x * 32, by = blockIdx.y * 32;
    const int txx = threadIdx.x;
    for (int j = threadIdx.y; j < 32; j += 8)
        t[j][txx] = S[(size_t)(by + j) * DMODEL + bx + txx];
    __syncthreads();
    for (int j = threadIdx.y; j < 32; j += 8)
        Dz[(size_t)(bx + j) * DMODEL + by + txx] = to_tf32(t[txx][j]);
}

// ---------------------------------------------------------------------------
// tf32 warp-MMA GEMM, 3-stage cp.async ring, ONE barrier per chunk.
// C = A[M,K] @ BT[N,K]^T (+bias). Block 128x128, BK=32, 8 warps (4x2).
// Dynamic smem: 3 x (As[128x36] + Bs[128x36]) = 110,592 B (2 CTAs/SM).
// ---------------------------------------------------------------------------
#define AS_STRIDE 36
#define GBUF (128 * AS_STRIDE)              // floats per tile
#define GSM_TOTAL (6 * GBUF * 4)            // bytes: 3 stages x (A+B)
#define NCHUNK (DMODEL / 32)                // 32

template<int FUSED, int ADD_BIAS, int ROUND_OUT>
__global__ void __launch_bounds__(256)
tf32_gemm_kernel(const float* __restrict__ A, const float* __restrict__ BT0,
                 const float* __restrict__ bias,
                 float* __restrict__ C0, float* __restrict__ C1,
                 float* __restrict__ C2)
{
    extern __shared__ float gsm[];
    float* Asb[3] = { gsm,            gsm + 2 * GBUF, gsm + 4 * GBUF };
    float* Bsb[3] = { gsm + GBUF,     gsm + 3 * GBUF, gsm + 5 * GBUF };

    const int tid  = threadIdx.x;
    const int wid  = tid >> 5;
    const int lane = tid & 31;
    const int wm   = wid & 3;
    const int wn   = wid >> 2;
    const int gid  = lane >> 2;
    const int tg   = lane & 3;
    const int rowA = blockIdx.y * 128;

    int which = 0, bx = blockIdx.x;
    if (FUSED) { which = blockIdx.x >> 3; bx = blockIdx.x & 7; }
    const int colB = bx * 128;
    const float* BT = BT0 + (size_t)which * DMODEL * DMODEL;
    float* C = (which == 0) ? C0 : (which == 1) ? C1 : C2;

    const int lr[4] = { tid >> 3, (tid + 256) >> 3, (tid + 512) >> 3, (tid + 768) >> 3 };
    const int lc = (tid & 7) * 4;

    float c[2][8][4];
#pragma unroll
    for (int mt = 0; mt < 2; ++mt)
#pragma unroll
        for (int nt = 0; nt < 8; ++nt)
#pragma unroll
            for (int r = 0; r < 4; ++r) c[mt][nt][r] = 0.f;

    // prologue: prefetch chunks 0 and 1 (one commit group each)
#pragma unroll
    for (int p = 0; p < 2; ++p) {
        const int kn = p * 32;
#pragma unroll
        for (int i = 0; i < 4; ++i) {
            cp16(Asb[p] + lr[i] * AS_STRIDE + lc, A  + (size_t)(rowA + lr[i]) * DMODEL + kn + lc);
            cp16(Bsb[p] + lr[i] * AS_STRIDE + lc, BT + (size_t)(colB + lr[i]) * DMODEL + kn + lc);
        }
        CP_COMMIT();
    }

    for (int cch = 0; cch < NCHUNK; ++cch) {
        const int buf = cch % 3;
        if (cch < NCHUNK - 1) { CP_WAIT(1); } else { CP_WAIT(0); }  // chunk cch ready
        __syncthreads();   // all warps done with chunk cch-1's buffer

        if (cch + 2 < NCHUNK) {    // prefetch chunk cch+2 into buffer (cch+2)%3
            const int nbuf = (cch + 2) % 3;
            const int kn = (cch + 2) * 32;
#pragma unroll
            for (int i = 0; i < 4; ++i) {
                cp16(Asb[nbuf] + lr[i] * AS_STRIDE + lc,
                     A  + (size_t)(rowA + lr[i]) * DMODEL + kn + lc);
                cp16(Bsb[nbuf] + lr[i] * AS_STRIDE + lc,
                     BT + (size_t)(colB + lr[i]) * DMODEL + kn + lc);
            }
            CP_COMMIT();
        }

        const float* As = Asb[buf];
        const float* Bs = Bsb[buf];
#pragma unroll
        for (int ks = 0; ks < 4; ++ks) {
            const int kb = ks * 8;
            uint32_t a[2][4], b[8][2];
#pragma unroll
            for (int mt = 0; mt < 2; ++mt) {
                const int mb = wm * 32 + mt * 16;
                a[mt][0] = __float_as_uint(As[(mb + gid    ) * AS_STRIDE + kb + tg    ]);
                a[mt][1] = __float_as_uint(As[(mb + gid + 8) * AS_STRIDE + kb + tg    ]);
                a[mt][2] = __float_as_uint(As[(mb + gid    ) * AS_STRIDE + kb + tg + 4]);
                a[mt][3] = __float_as_uint(As[(mb + gid + 8) * AS_STRIDE + kb + tg + 4]);
            }
#pragma unroll
            for (int nt = 0; nt < 8; ++nt) {
                const int nb = wn * 64 + nt * 8;
                b[nt][0] = __float_as_uint(Bs[(nb + gid) * AS_STRIDE + kb + tg    ]);
                b[nt][1] = __float_as_uint(Bs[(nb + gid) * AS_STRIDE + kb + tg + 4]);
            }
#pragma unroll
            for (int mt = 0; mt < 2; ++mt)
#pragma unroll
                for (int nt = 0; nt < 8; ++nt)
                    MMA_TF32(c[mt][nt][0], c[mt][nt][1], c[mt][nt][2], c[mt][nt][3],
                             a[mt][0], a[mt][1], a[mt][2], a[mt][3],
                             b[nt][0], b[nt][1]);
        }
    }

#pragma unroll
    for (int mt = 0; mt < 2; ++mt) {
        const int r0 = rowA + wm * 32 + mt * 16 + gid;
#pragma unroll
        for (int nt = 0; nt < 8; ++nt) {
            const int col = colB + wn * 64 + nt * 8 + tg * 2;
            float bxv = 0.f, byv = 0.f;
            if (ADD_BIAS) { bxv = bias[col]; byv = bias[col + 1]; }
            float2 lo = make_float2(c[mt][nt][0] + bxv, c[mt][nt][1] + byv);
            float2 hi = make_float2(c[mt][nt][2] + bxv, c[mt][nt][3] + byv);
            if (ROUND_OUT) {
                lo.x = to_tf32(lo.x); lo.y = to_tf32(lo.y);
                hi.x = to_tf32(hi.x); hi.y = to_tf32(hi.y);
            }
            *(float2*)(C + (size_t)r0 * DMODEL + col)       = lo;
            *(float2*)(C + (size_t)(r0 + 8) * DMODEL + col) = hi;
        }
    }
}

// ---------------------------------------------------------------------------
// Flash attention, tf32 mma. R14: ONE barrier per key tile (2-buffer ring;
// wait tile kt -> barrier -> issue kt+1 -> compute). Numerics as R13:
// register-P (V rows permuted by pi), exp2-domain softmax, masked-warp skip.
// smem: QPs[128][68] (Q staging), Ks[2][64][68], Vs[2][64][72].
// ---------------------------------------------------------------------------
#define FS  68
#define FSV 72
#define F_KS   (128 * FS)
#define F_VS   (F_KS + 2 * 64 * FS)
#define F_TOTAL (F_VS + 2 * 64 * FSV)   // 26,624 floats = 106,496 B

__global__ void __launch_bounds__(256, 2)
flash_mma_kernel(const float* __restrict__ q, const float* __restrict__ k,
                 const float* __restrict__ v, float* __restrict__ ctx)
{
    extern __shared__ float smf[];
    float* QPs = smf;
    float* Ksb[2] = { smf + F_KS, smf + F_KS + 64 * FS };
    float* Vsb[2] = { smf + F_VS, smf + F_VS + 64 * FSV };

    const int qt  = (int)gridDim.x - 1 - (int)blockIdx.x;   // heavy first
    const int bh  = blockIdx.y;
    const int b   = bh >> 4;
    const int h   = bh & 15;
    const int q0  = qt * 128;
    const int tid = threadIdx.x;
    const int wid = tid >> 5;
    const int lane = tid & 31;
    const int gid = lane >> 2;
    const int tg  = lane & 3;
    const int r0  = wid * 16 + gid;
    const int r1  = r0 + 8;

    const float* kbh = k + (size_t)b * SEQ * DMODEL + h * HDIM;
    const float* vbh = v + (size_t)b * SEQ * DMODEL + h * HDIM;

    const int ldrow[4] = { (tid + 0) >> 4, (tid + 256) >> 4,
                           (tid + 512) >> 4, (tid + 768) >> 4 };
    const int ldch = tid & 15;
    // V destination rows permuted within 8-row groups: pi(r)=4(r&1)+(r>>1)
    int vrow[4];
#pragma unroll
    for (int i = 0; i < 4; ++i) {
        int r8 = ldrow[i] & 7;
        vrow[i] = (ldrow[i] & 56) | (((r8 & 1) << 2) | (r8 >> 1));
    }

    // ---- prefetch tile 0 ----
#pragma unroll
    for (int i = 0; i < 4; ++i) {
        cp16(Ksb[0] + ldrow[i] * FS  + ldch * 4, kbh + (size_t)ldrow[i] * DMODEL + ldch * 4);
        cp16(Vsb[0] + vrow[i]  * FSV + ldch * 4, vbh + (size_t)ldrow[i] * DMODEL + ldch * 4);
    }
    CP_COMMIT();

    // ---- stage Q tile, hoist fragments, fold scale*log2e into Q ----
    const float* qbase = q + ((size_t)b * SEQ + q0) * DMODEL + h * HDIM;
    for (int it = tid; it < 128 * 16; it += 256) {
        int row = it >> 4, c4 = it & 15;
        *(float4*)&QPs[row * FS + c4 * 4] =
            *(const float4*)(qbase + (size_t)row * DMODEL + c4 * 4);
    }
    __syncthreads();
    const float csc = 0.18033688011112042f;   // 0.125 * log2(e)
    uint32_t qf[8][4];
#pragma unroll
    for (int ks = 0; ks < 8; ++ks) {
        const int kb = ks * 8;
        qf[ks][0] = __float_as_uint(to_tf32(QPs[r0 * FS + kb + tg    ] * csc));
        qf[ks][1] = __float_as_uint(to_tf32(QPs[r1 * FS + kb + tg    ] * csc));
        qf[ks][2] = __float_as_uint(to_tf32(QPs[r0 * FS + kb + tg + 4] * csc));
        qf[ks][3] = __float_as_uint(to_tf32(QPs[r1 * FS + kb + tg + 4] * csc));
    }

    float m0 = -INFINITY, m1 = -INFINITY, l0 = 0.f, l1 = 0.f;
    float o[8][4];
#pragma unroll
    for (int nt = 0; nt < 8; ++nt)
#pragma unroll
        for (int r = 0; r < 4; ++r) o[nt][r] = 0.f;

    const int ktmax = 2 * qt + 1;
    for (int kt = 0; kt <= ktmax; ++kt) {
        const int buf = kt & 1;
        CP_WAIT(0);        // tile kt arrived (only pending group)
        __syncthreads();   // data visible; all warps done with buf^1 (tile kt-1)

        if (kt < ktmax) {  // prefetch tile kt+1 into the freed buffer
            const float* kbn = kbh + (size_t)(kt + 1) * 64 * DMODEL;
            const float* vbn = vbh + (size_t)(kt + 1) * 64 * DMODEL;
            float* Kd = Ksb[buf ^ 1];
            float* Vd = Vsb[buf ^ 1];
#pragma unroll
            for (int i = 0; i < 4; ++i) {
                cp16(Kd + ldrow[i] * FS  + ldch * 4, kbn + (size_t)ldrow[i] * DMODEL + ldch * 4);
                cp16(Vd + vrow[i]  * FSV + ldch * 4, vbn + (size_t)ldrow[i] * DMODEL + ldch * 4);
            }
            CP_COMMIT();
        }

        const bool maskt = (kt >= 2 * qt);
        const int colbase = (kt - 2 * qt) * 64;        // 0 or 64 when maskt
        if (maskt && colbase > wid * 16 + 15) continue; // fully masked warp

        const float* Ks = Ksb[buf];
        const float* Vs = Vsb[buf];

        // ---- S (log2-domain) = (Q*csc) K^T ----
        float s[8][4];
#pragma unroll
        for (int nt = 0; nt < 8; ++nt)
#pragma unroll
            for (int r = 0; r < 4; ++r) s[nt][r] = 0.f;
#pragma unroll
        for (int ks = 0; ks < 8; ++ks) {
            const int kb = ks * 8;
#pragma unroll
            for (int nt = 0; nt < 8; ++nt) {
                uint32_t b0 = __float_as_uint(Ks[(nt * 8 + gid) * FS + kb + tg    ]);
                uint32_t b1 = __float_as_uint(Ks[(nt * 8 + gid) * FS + kb + tg + 4]);
                MMA_TF32(s[nt][0], s[nt][1], s[nt][2], s[nt][3],
                         qf[ks][0], qf[ks][1], qf[ks][2], qf[ks][3], b0, b1);
            }
        }

        // ---- causal mask + row max (log2 domain) ----
        float tm0 = -INFINITY, tm1 = -INFINITY;
#pragma unroll
        for (int nt = 0; nt < 8; ++nt) {
            float s0 = s[nt][0], s1 = s[nt][1], s2 = s[nt][2], s3 = s[nt][3];
            if (maskt) {
                int c0 = colbase + nt * 8 + 2 * tg, c1 = c0 + 1;
                if (c0 > r0) s0 = -INFINITY;
                if (c1 > r0) s1 = -INFINITY;
                if (c0 > r1) s2 = -INFINITY;
                if (c1 > r1) s3 = -INFINITY;
                s[nt][0] = s0; s[nt][1] = s1; s[nt][2] = s2; s[nt][3] = s3;
            }
            tm0 = fmaxf(tm0, fmaxf(s0, s1));
            tm1 = fmaxf(tm1, fmaxf(s2, s3));
        }
        tm0 = fmaxf(tm0, __shfl_xor_sync(0xffffffffu, tm0, 1));
        tm0 = fmaxf(tm0, __shfl_xor_sync(0xffffffffu, tm0, 2));
        tm1 = fmaxf(tm1, __shfl_xor_sync(0xffffffffu, tm1, 1));
        tm1 = fmaxf(tm1, __shfl_xor_sync(0xffffffffu, tm1, 2));

        const float mn0 = fmaxf(m0, tm0), mn1 = fmaxf(m1, tm1);
        const float alpha0 = ex2f(m0 - mn0), alpha1 = ex2f(m1 - mn1);
        float rs0 = 0.f, rs1 = 0.f;
#pragma unroll
        for (int nt = 0; nt < 8; ++nt) {
            float p0 = to_tf32(ex2f(s[nt][0] - mn0));
            float p1 = to_tf32(ex2f(s[nt][1] - mn0));
            float p2 = to_tf32(ex2f(s[nt][2] - mn1));
            float p3 = to_tf32(ex2f(s[nt][3] - mn1));
            rs0 += p0 + p1;  rs1 += p2 + p3;
            s[nt][0] = p0; s[nt][1] = p1; s[nt][2] = p2; s[nt][3] = p3;
        }
        rs0 += __shfl_xor_sync(0xffffffffu, rs0, 1);
        rs0 += __shfl_xor_sync(0xffffffffu, rs0, 2);
        rs1 += __shfl_xor_sync(0xffffffffu, rs1, 1);
        rs1 += __shfl_xor_sync(0xffffffffu, rs1, 2);

        l0 = l0 * alpha0 + rs0;  m0 = mn0;
        l1 = l1 * alpha1 + rs1;  m1 = mn1;
#pragma unroll
        for (int nt = 0; nt < 8; ++nt) {
            o[nt][0] *= alpha0; o[nt][1] *= alpha0;
            o[nt][2] *= alpha1; o[nt][3] *= alpha1;
        }

        // ---- O += P V' : A-fragments ARE s[] (V rows pre-permuted by pi) ----
#pragma unroll
        for (int ks = 0; ks < 8; ++ks) {
            const int kb = ks * 8;
            uint32_t a0 = __float_as_uint(s[ks][0]);   // P'[r0][kb+tg]
            uint32_t a1 = __float_as_uint(s[ks][2]);   // P'[r1][kb+tg]
            uint32_t a2 = __float_as_uint(s[ks][1]);   // P'[r0][kb+tg+4]
            uint32_t a3 = __float_as_uint(s[ks][3]);   // P'[r1][kb+tg+4]
#pragma unroll
            for (int nt = 0; nt < 8; ++nt) {
                uint32_t b0 = __float_as_uint(Vs[(kb + tg    ) * FSV + nt * 8 + gid]);
                uint32_t b1 = __float_as_uint(Vs[(kb + tg + 4) * FSV + nt * 8 + gid]);
                MMA_TF32(o[nt][0], o[nt][1], o[nt][2], o[nt][3],
                         a0, a1, a2, a3, b0, b1);
            }
        }
    }

    // ---- write O (pre-rounded to tf32 for the output GEMM) ----
    const float inv0 = 1.f / l0, inv1 = 1.f / l1;
    float* ob0 = ctx + ((size_t)b * SEQ + q0 + r0) * DMODEL + h * HDIM;
    float* ob1 = ctx + ((size_t)b * SEQ + q0 + r1) * DMODEL + h * HDIM;
#pragma unroll
    for (int nt = 0; nt < 8; ++nt) {
        const int cc = nt * 8 + 2 * tg;
        *(float2*)(ob0 + cc) = make_float2(to_tf32(o[nt][0] * inv0),
                                           to_tf32(o[nt][1] * inv0));
        *(float2*)(ob1 + cc) = make_float2(to_tf32(o[nt][2] * inv1),
                                           to_tf32(o[nt][3] * inv1));
    }
}

// ---------------------------------------------------------------------------
// Launch: round(x) + transpose -> fused QKV GEMM -> flash -> out GEMM + bias
// ---------------------------------------------------------------------------
extern "C" void kernel_launch(void* const* d_in, const int* in_sizes, int n_in,
                              void* d_out, int out_size)
{
    const float* x  = (const float*)d_in[0];
    const float* Wq = (const float*)d_in[1];
    const float* Wk = (const float*)d_in[2];
    const float* Wv = (const float*)d_in[3];
    const float* Wo = (const float*)d_in[4];
    const float* bo = (const float*)d_in[5];
    float* out = (float*)d_out;

    float *pq, *pk, *pv, *pc, *pw, *pxr;
    cudaGetSymbolAddress((void**)&pq, g_q);
    cudaGetSymbolAddress((void**)&pk, g_k);
    cudaGetSymbolAddress((void**)&pv, g_v);
    cudaGetSymbolAddress((void**)&pc, g_ctx);
    cudaGetSymbolAddress((void**)&pw, g_wT);
    cudaGetSymbolAddress((void**)&pxr, g_xr);

    round_kernel<<<MTOT * DMODEL / 4 / 256, 256>>>(x, pxr);
    transpose_round4_kernel<<<dim3(DMODEL / 32, DMODEL / 32, 4), dim3(32, 8)>>>(
        Wq, Wk, Wv, Wo, pw);

    cudaFuncSetAttribute(tf32_gemm_kernel<1, 0, 1>,
                         cudaFuncAttributeMaxDynamicSharedMemorySize, GSM_TOTAL);
    cudaFuncSetAttribute(tf32_gemm_kernel<0, 1, 0>,
                         cudaFuncAttributeMaxDynamicSharedMemorySize, GSM_TOTAL);

    tf32_gemm_kernel<1, 0, 1><<<dim3(24, MTOT / 128), 256, GSM_TOTAL>>>(
        pxr, pw, nullptr, pq, pk, pv);

    size_t smem = F_TOTAL * sizeof(float);   // 106,496 B
    cudaFuncSetAttribute(flash_mma_kernel,
                         cudaFuncAttributeMaxDynamicSharedMemorySize, (int)smem);
    flash_mma_kernel<<<dim3(SEQ / 128, BATCH * NHEAD), 256, smem>>>(pq, pk, pv, pc);

    tf32_gemm_kernel<0, 1, 0><<<dim3(8, MTOT / 128), 256, GSM_TOTAL>>>(
        pc, pw + 3 * (size_t)DMODEL * DMODEL, bo, out, nullptr, nullptr);
}

// round 15
// speedup vs baseline: 1.1057x; 1.1057x over previous
#include <cuda_runtime.h>
#include <math.h>
#include <stdint.h>

// ---------------------------------------------------------------------------
// MHA: x[2,2048,1024], 16 heads x 64, causal, fp32 I/O.
// R15: sigma-permuted contraction dims everywhere -> all MMA fragment loads
//      become float2 (GEMM mainloop LDS -50%, flash S-side LDS -50%).
//      sigma(c) = c<4 ? 2c : 2(c-4)+1 within each 8-group; strides chosen
//      == 8 (mod 32) so float2 LDS are phase-conflict-free.
//      Flash restored to R13 ordering (early prefetch issue — R14 lesson).
//      Numerics bit-identical to R13 (values map to the same MMA k-slots).
// ---------------------------------------------------------------------------
#define BATCH   2
#define SEQ     2048
#define DMODEL  1024
#define NHEAD   16
#define HDIM    64
#define MTOT    (BATCH * SEQ)          // 4096 rows

__device__ float g_q[MTOT * DMODEL];
__device__ float g_k[MTOT * DMODEL];
__device__ float g_v[MTOT * DMODEL];
__device__ float g_ctx[MTOT * DMODEL];
__device__ float g_xr[MTOT * DMODEL];        // tf32-rounded, sigma-permuted x
__device__ float g_wT[4][DMODEL * DMODEL];   // transposed+rounded, sigma-k weights

__device__ __forceinline__ float to_tf32(float x) {
    uint32_t i = __float_as_uint(x), o;
    asm("cvt.rna.tf32.f32 %0, %1;" : "=r"(o) : "r"(i));
    return __uint_as_float(o);
}
__device__ __forceinline__ float ex2f(float x) {
    float y;
    asm("ex2.approx.ftz.f32 %0, %1;" : "=f"(y) : "f"(x));
    return y;
}
__device__ __forceinline__ int sig8(int c) {   // permute within an 8-group
    return (c & 4) ? 2 * (c & 3) + 1 : 2 * c;
}

#define MMA_TF32(c0, c1, c2, c3, a0, a1, a2, a3, b0, b1)                     \
    asm volatile("mma.sync.aligned.m16n8k8.row.col.f32.tf32.tf32.f32 "       \
                 "{%0,%1,%2,%3}, {%4,%5,%6,%7}, {%8,%9}, {%0,%1,%2,%3};"     \
                 : "+f"(c0), "+f"(c1), "+f"(c2), "+f"(c3)                    \
                 : "r"(a0), "r"(a1), "r"(a2), "r"(a3), "r"(b0), "r"(b1))

__device__ __forceinline__ void cp16(float* dst, const float* src) {
    uint32_t d = (uint32_t)__cvta_generic_to_shared(dst);
    asm volatile("cp.async.ca.shared.global [%0], [%1], 16;" :: "r"(d), "l"(src));
}
#define CP_COMMIT()  asm volatile("cp.async.commit_group;" ::: "memory")
#define CP_WAIT(n)   asm volatile("cp.async.wait_group %0;" :: "n"(n) : "memory")

// ---------------------------------------------------------------------------
// x -> tf32-rounded + sigma-permuted columns. 8 cols per thread.
// dest group: (v0,v4,v1,v5, v2,v6,v3,v7)
// ---------------------------------------------------------------------------
__global__ void __launch_bounds__(256)
round_kernel(const float* __restrict__ src, float* __restrict__ dst)
{
    size_t base = (size_t)(blockIdx.x * 256 + threadIdx.x) * 8;
    float4 lo = *(const float4*)(src + base);
    float4 hi = *(const float4*)(src + base + 4);
    float4 o0 = make_float4(to_tf32(lo.x), to_tf32(hi.x), to_tf32(lo.y), to_tf32(hi.y));
    float4 o1 = make_float4(to_tf32(lo.z), to_tf32(hi.z), to_tf32(lo.w), to_tf32(hi.w));
    *(float4*)(dst + base)     = o0;
    *(float4*)(dst + base + 4) = o1;
}

// ---------------------------------------------------------------------------
// Fused weight transpose + tf32 round + sigma on the k index (grid.z = 4).
// D[n][sig(k)] = tf32(S[k][n])
// ---------------------------------------------------------------------------
__global__ void __launch_bounds__(256)
transpose_round4_kernel(const float* __restrict__ S0, const float* __restrict__ S1,
                        const float* __restrict__ S2, const float* __restrict__ S3,
                        float* __restrict__ D)
{
    __shared__ float t[32][33];
    const int z = blockIdx.z;
    const float* S = (z == 0) ? S0 : (z == 1) ? S1 : (z == 2) ? S2 : S3;
    float* Dz = D + (size_t)z * DMODEL * DMODEL;
    const int bx = blockIdx.x * 32, by = blockIdx.y * 32;
    const int txx = threadIdx.x;
    for (int j = threadIdx.y; j < 32; j += 8)
        t[j][txx] = S[(size_t)(by + j) * DMODEL + bx + txx];
    __syncthreads();
    const int ksig = (txx & ~7) | sig8(txx & 7);
    for (int j = threadIdx.y; j < 32; j += 8)
        Dz[(size_t)(bx + j) * DMODEL + by + ksig] = to_tf32(t[txx][j]);
}

// ---------------------------------------------------------------------------
// tf32 warp-MMA GEMM, 2-stage cp.async (R10 ordering), sigma-permuted inputs:
// all A/B fragment loads are float2. Stride 40 (== 8 mod 32, conflict-free).
// ROUND_OUT=1 (QKV): outputs written tf32-rounded AND sigma-permuted cols.
// ROUND_OUT=0 (out): natural columns + bias.
// ---------------------------------------------------------------------------
#define AS_STRIDE 40
#define GBUF (128 * AS_STRIDE)
#define GSM_TOTAL (4 * GBUF * 4)        // 2 stages x (A+B) = 81,920 B

template<int FUSED, int ADD_BIAS, int ROUND_OUT>
__global__ void __launch_bounds__(256)
tf32_gemm_kernel(const float* __restrict__ A, const float* __restrict__ BT0,
                 const float* __restrict__ bias,
                 float* __restrict__ C0, float* __restrict__ C1,
                 float* __restrict__ C2)
{
    extern __shared__ float gsm[];
    float* Asb[2] = { gsm,        gsm + 2 * GBUF };
    float* Bsb[2] = { gsm + GBUF, gsm + 3 * GBUF };

    const int tid  = threadIdx.x;
    const int wid  = tid >> 5;
    const int lane = tid & 31;
    const int wm   = wid & 3;
    const int wn   = wid >> 2;
    const int gid  = lane >> 2;
    const int tg   = lane & 3;
    const int rowA = blockIdx.y * 128;

    int which = 0, bx = blockIdx.x;
    if (FUSED) { which = blockIdx.x >> 3; bx = blockIdx.x & 7; }
    const int colB = bx * 128;
    const float* BT = BT0 + (size_t)which * DMODEL * DMODEL;
    float* C = (which == 0) ? C0 : (which == 1) ? C1 : C2;

    const int lr[4] = { tid >> 3, (tid + 256) >> 3, (tid + 512) >> 3, (tid + 768) >> 3 };
    const int lc = (tid & 7) * 4;

    float c[2][8][4];
#pragma unroll
    for (int mt = 0; mt < 2; ++mt)
#pragma unroll
        for (int nt = 0; nt < 8; ++nt)
#pragma unroll
            for (int r = 0; r < 4; ++r) c[mt][nt][r] = 0.f;

    // prologue: prefetch chunk 0
#pragma unroll
    for (int i = 0; i < 4; ++i) {
        cp16(Asb[0] + lr[i] * AS_STRIDE + lc, A  + (size_t)(rowA + lr[i]) * DMODEL + lc);
        cp16(Bsb[0] + lr[i] * AS_STRIDE + lc, BT + (size_t)(colB + lr[i]) * DMODEL + lc);
    }
    CP_COMMIT();

    for (int cch = 0; cch < DMODEL / 32; ++cch) {
        const int buf = cch & 1;
        if (cch + 1 < DMODEL / 32) {     // early issue, then wait (R13 lesson)
            const int kn = (cch + 1) * 32;
#pragma unroll
            for (int i = 0; i < 4; ++i) {
                cp16(Asb[buf ^ 1] + lr[i] * AS_STRIDE + lc,
                     A  + (size_t)(rowA + lr[i]) * DMODEL + kn + lc);
                cp16(Bsb[buf ^ 1] + lr[i] * AS_STRIDE + lc,
                     BT + (size_t)(colB + lr[i]) * DMODEL + kn + lc);
            }
            CP_COMMIT();
            CP_WAIT(1);
        } else {
            CP_WAIT(0);
        }
        __syncthreads();

        const float* As = Asb[buf];
        const float* Bs = Bsb[buf];
#pragma unroll
        for (int ks = 0; ks < 4; ++ks) {
            const int kb = ks * 8;
            uint32_t a[2][4], b[8][2];
#pragma unroll
            for (int mt = 0; mt < 2; ++mt) {
                const int mb = wm * 32 + mt * 16;
                float2 A0 = *(const float2*)&As[(mb + gid    ) * AS_STRIDE + kb + 2 * tg];
                float2 A1 = *(const float2*)&As[(mb + gid + 8) * AS_STRIDE + kb + 2 * tg];
                a[mt][0] = __float_as_uint(A0.x);   // k = tg
                a[mt][1] = __float_as_uint(A1.x);
                a[mt][2] = __float_as_uint(A0.y);   // k = tg+4
                a[mt][3] = __float_as_uint(A1.y);
            }
#pragma unroll
            for (int nt = 0; nt < 8; ++nt) {
                const int nb = wn * 64 + nt * 8;
                float2 B0 = *(const float2*)&Bs[(nb + gid) * AS_STRIDE + kb + 2 * tg];
                b[nt][0] = __float_as_uint(B0.x);
                b[nt][1] = __float_as_uint(B0.y);
            }
#pragma unroll
            for (int mt = 0; mt < 2; ++mt)
#pragma unroll
                for (int nt = 0; nt < 8; ++nt)
                    MMA_TF32(c[mt][nt][0], c[mt][nt][1], c[mt][nt][2], c[mt][nt][3],
                             a[mt][0], a[mt][1], a[mt][2], a[mt][3],
                             b[nt][0], b[nt][1]);
        }
        __syncthreads();
    }

#pragma unroll
    for (int mt = 0; mt < 2; ++mt) {
        const int r0 = rowA + wm * 32 + mt * 16 + gid;
#pragma unroll
        for (int nt = 0; nt < 8; ++nt) {
            if (ROUND_OUT) {
                // sigma-permuted output columns (QKV): scatter scalars
                const int base = colB + wn * 64 + nt * 8;
                const int d0 = base + sig8(2 * tg);
                const int d1 = base + sig8(2 * tg + 1);
                C[(size_t)r0 * DMODEL + d0]       = to_tf32(c[mt][nt][0]);
                C[(size_t)r0 * DMODEL + d1]       = to_tf32(c[mt][nt][1]);
                C[(size_t)(r0 + 8) * DMODEL + d0] = to_tf32(c[mt][nt][2]);
                C[(size_t)(r0 + 8) * DMODEL + d1] = to_tf32(c[mt][nt][3]);
            } else {
                const int col = colB + wn * 64 + nt * 8 + tg * 2;
                float bxv = 0.f, byv = 0.f;
                if (ADD_BIAS) { bxv = bias[col]; byv = bias[col + 1]; }
                *(float2*)(C + (size_t)r0 * DMODEL + col) =
                    make_float2(c[mt][nt][0] + bxv, c[mt][nt][1] + byv);
                *(float2*)(C + (size_t)(r0 + 8) * DMODEL + col) =
                    make_float2(c[mt][nt][2] + bxv, c[mt][nt][3] + byv);
            }
        }
    }
}

// ---------------------------------------------------------------------------
// Flash attention, tf32 mma. R13 ordering (early prefetch issue, 2 barriers).
// q/k arrive sigma-permuted in d -> K b-frags and Q frags are float2.
// All strides 72 (== 8 mod 32: float2 loads conflict-free; V scalar pattern
// 8*tg+gid also conflict-free). Register-P via V row-permutation pi,
// exp2-domain softmax, masked-warp skip. ctx written tf32 (inherits sigma
// from v's columns -> feeds the out-GEMM's sigma contraction).
// smem: QPs[128][72], Ks[2][64][72], Vs[2][64][72] = 110,592 B (2 CTAs/SM).
// ---------------------------------------------------------------------------
#define FS  72
#define F_KS   (128 * FS)
#define F_VS   (F_KS + 2 * 64 * FS)
#define F_TOTAL (F_VS + 2 * 64 * FS)   // 27,648 floats = 110,592 B

__global__ void __launch_bounds__(256, 2)
flash_mma_kernel(const float* __restrict__ q, const float* __restrict__ k,
                 const float* __restrict__ v, float* __restrict__ ctx)
{
    extern __shared__ float smf[];
    float* QPs = smf;
    float* Ksb[2] = { smf + F_KS, smf + F_KS + 64 * FS };
    float* Vsb[2] = { smf + F_VS, smf + F_VS + 64 * FS };

    const int qt  = (int)gridDim.x - 1 - (int)blockIdx.x;   // heavy first
    const int bh  = blockIdx.y;
    const int b   = bh >> 4;
    const int h   = bh & 15;
    const int q0  = qt * 128;
    const int tid = threadIdx.x;
    const int wid = tid >> 5;
    const int lane = tid & 31;
    const int gid = lane >> 2;
    const int tg  = lane & 3;
    const int r0  = wid * 16 + gid;
    const int r1  = r0 + 8;

    const float* kbh = k + (size_t)b * SEQ * DMODEL + h * HDIM;
    const float* vbh = v + (size_t)b * SEQ * DMODEL + h * HDIM;

    const int ldrow[4] = { (tid + 0) >> 4, (tid + 256) >> 4,
                           (tid + 512) >> 4, (tid + 768) >> 4 };
    const int ldch = tid & 15;
    // V destination rows permuted within 8-row groups: pi(r)=4(r&1)+(r>>1)
    int vrow[4];
#pragma unroll
    for (int i = 0; i < 4; ++i) {
        int r8 = ldrow[i] & 7;
        vrow[i] = (ldrow[i] & 56) | (((r8 & 1) << 2) | (r8 >> 1));
    }

    // ---- prefetch tile 0 ----
#pragma unroll
    for (int i = 0; i < 4; ++i) {
        cp16(Ksb[0] + ldrow[i] * FS + ldch * 4, kbh + (size_t)ldrow[i] * DMODEL + ldch * 4);
        cp16(Vsb[0] + vrow[i]  * FS + ldch * 4, vbh + (size_t)ldrow[i] * DMODEL + ldch * 4);
    }
    CP_COMMIT();

    // ---- stage Q tile, hoist fragments (float2: sigma pairs), fold scale ----
    const float* qbase = q + ((size_t)b * SEQ + q0) * DMODEL + h * HDIM;
    for (int it = tid; it < 128 * 16; it += 256) {
        int row = it >> 4, c4 = it & 15;
        *(float4*)&QPs[row * FS + c4 * 4] =
            *(const float4*)(qbase + (size_t)row * DMODEL + c4 * 4);
    }
    __syncthreads();
    const float csc = 0.18033688011112042f;   // 0.125 * log2(e)
    uint32_t qf[8][4];
#pragma unroll
    for (int ks = 0; ks < 8; ++ks) {
        const int kb = ks * 8;
        float2 Q0 = *(const float2*)&QPs[r0 * FS + kb + 2 * tg];
        float2 Q1 = *(const float2*)&QPs[r1 * FS + kb + 2 * tg];
        qf[ks][0] = __float_as_uint(to_tf32(Q0.x * csc));   // k = tg
        qf[ks][1] = __float_as_uint(to_tf32(Q1.x * csc));
        qf[ks][2] = __float_as_uint(to_tf32(Q0.y * csc));   // k = tg+4
        qf[ks][3] = __float_as_uint(to_tf32(Q1.y * csc));
    }

    float m0 = -INFINITY, m1 = -INFINITY, l0 = 0.f, l1 = 0.f;
    float o[8][4];
#pragma unroll
    for (int nt = 0; nt < 8; ++nt)
#pragma unroll
        for (int r = 0; r < 4; ++r) o[nt][r] = 0.f;

    const int ktmax = 2 * qt + 1;
    for (int kt = 0; kt <= ktmax; ++kt) {
        const int buf = kt & 1;
        __syncthreads();   // all warps done with buf^1 (tile kt-1) and QPs reads
        if (kt < ktmax) {  // early issue of tile kt+1, THEN wait on tile kt
            const float* kbn = kbh + (size_t)(kt + 1) * 64 * DMODEL;
            const float* vbn = vbh + (size_t)(kt + 1) * 64 * DMODEL;
            float* Kd = Ksb[buf ^ 1];
            float* Vd = Vsb[buf ^ 1];
#pragma unroll
            for (int i = 0; i < 4; ++i) {
                cp16(Kd + ldrow[i] * FS + ldch * 4, kbn + (size_t)ldrow[i] * DMODEL + ldch * 4);
                cp16(Vd + vrow[i]  * FS + ldch * 4, vbn + (size_t)ldrow[i] * DMODEL + ldch * 4);
            }
            CP_COMMIT();
            CP_WAIT(1);
        } else {
            CP_WAIT(0);
        }
        __syncthreads();

        const bool maskt = (kt >= 2 * qt);
        const int colbase = (kt - 2 * qt) * 64;        // 0 or 64 when maskt
        if (maskt && colbase > wid * 16 + 15) continue; // fully masked warp

        const float* Ks = Ksb[buf];
        const float* Vs = Vsb[buf];

        // ---- S (log2-domain) = (Q*csc) K^T : float2 b-frags ----
        float s[8][4];
#pragma unroll
        for (int nt = 0; nt < 8; ++nt)
#pragma unroll
            for (int r = 0; r < 4; ++r) s[nt][r] = 0.f;
#pragma unroll
        for (int ks = 0; ks < 8; ++ks) {
            const int kb = ks * 8;
#pragma unroll
            for (int nt = 0; nt < 8; ++nt) {
                float2 B0 = *(const float2*)&Ks[(nt * 8 + gid) * FS + kb + 2 * tg];
                MMA_TF32(s[nt][0], s[nt][1], s[nt][2], s[nt][3],
                         qf[ks][0], qf[ks][1], qf[ks][2], qf[ks][3],
                         __float_as_uint(B0.x), __float_as_uint(B0.y));
            }
        }

        // ---- causal mask + row max (log2 domain) ----
        float tm0 = -INFINITY, tm1 = -INFINITY;
#pragma unroll
        for (int nt = 0; nt < 8; ++nt) {
            float s0 = s[nt][0], s1 = s[nt][1], s2 = s[nt][2], s3 = s[nt][3];
            if (maskt) {
                int c0 = colbase + nt * 8 + 2 * tg, c1 = c0 + 1;
                if (c0 > r0) s0 = -INFINITY;
                if (c1 > r0) s1 = -INFINITY;
                if (c0 > r1) s2 = -INFINITY;
                if (c1 > r1) s3 = -INFINITY;
                s[nt][0] = s0; s[nt][1] = s1; s[nt][2] = s2; s[nt][3] = s3;
            }
            tm0 = fmaxf(tm0, fmaxf(s0, s1));
            tm1 = fmaxf(tm1, fmaxf(s2, s3));
        }
        tm0 = fmaxf(tm0, __shfl_xor_sync(0xffffffffu, tm0, 1));
        tm0 = fmaxf(tm0, __shfl_xor_sync(0xffffffffu, tm0, 2));
        tm1 = fmaxf(tm1, __shfl_xor_sync(0xffffffffu, tm1, 1));
        tm1 = fmaxf(tm1, __shfl_xor_sync(0xffffffffu, tm1, 2));

        const float mn0 = fmaxf(m0, tm0), mn1 = fmaxf(m1, tm1);
        const float alpha0 = ex2f(m0 - mn0), alpha1 = ex2f(m1 - mn1);
        float rs0 = 0.f, rs1 = 0.f;
#pragma unroll
        for (int nt = 0; nt < 8; ++nt) {
            float p0 = to_tf32(ex2f(s[nt][0] - mn0));
            float p1 = to_tf32(ex2f(s[nt][1] - mn0));
            float p2 = to_tf32(ex2f(s[nt][2] - mn1));
            float p3 = to_tf32(ex2f(s[nt][3] - mn1));
            rs0 += p0 + p1;  rs1 += p2 + p3;
            s[nt][0] = p0; s[nt][1] = p1; s[nt][2] = p2; s[nt][3] = p3;
        }
        rs0 += __shfl_xor_sync(0xffffffffu, rs0, 1);
        rs0 += __shfl_xor_sync(0xffffffffu, rs0, 2);
        rs1 += __shfl_xor_sync(0xffffffffu, rs1, 1);
        rs1 += __shfl_xor_sync(0xffffffffu, rs1, 2);

        l0 = l0 * alpha0 + rs0;  m0 = mn0;
        l1 = l1 * alpha1 + rs1;  m1 = mn1;
#pragma unroll
        for (int nt = 0; nt < 8; ++nt) {
            o[nt][0] *= alpha0; o[nt][1] *= alpha0;
            o[nt][2] *= alpha1; o[nt][3] *= alpha1;
        }

        // ---- O += P V' : A-fragments ARE s[] (V rows pre-permuted by pi) ----
#pragma unroll
        for (int ks = 0; ks < 8; ++ks) {
            const int kb = ks * 8;
            uint32_t a0 = __float_as_uint(s[ks][0]);
            uint32_t a1 = __float_as_uint(s[ks][2]);
            uint32_t a2 = __float_as_uint(s[ks][1]);
            uint32_t a3 = __float_as_uint(s[ks][3]);
#pragma unroll
            for (int nt = 0; nt < 8; ++nt) {
                uint32_t b0 = __float_as_uint(Vs[(kb + tg    ) * FS + nt * 8 + gid]);
                uint32_t b1 = __float_as_uint(Vs[(kb + tg + 4) * FS + nt * 8 + gid]);
                MMA_TF32(o[nt][0], o[nt][1], o[nt][2], o[nt][3],
                         a0, a1, a2, a3, b0, b1);
            }
        }
    }

    // ---- write O (tf32; columns inherit sigma from v -> out-GEMM matches) ----
    const float inv0 = 1.f / l0, inv1 = 1.f / l1;
    float* ob0 = ctx + ((size_t)b * SEQ + q0 + r0) * DMODEL + h * HDIM;
    float* ob1 = ctx + ((size_t)b * SEQ + q0 + r1) * DMODEL + h * HDIM;
#pragma unroll
    for (int nt = 0; nt < 8; ++nt) {
        const int cc = nt * 8 + 2 * tg;
        *(float2*)(ob0 + cc) = make_float2(to_tf32(o[nt][0] * inv0),
                                           to_tf32(o[nt][1] * inv0));
        *(float2*)(ob1 + cc) = make_float2(to_tf32(o[nt][2] * inv1),
                                           to_tf32(o[nt][3] * inv1));
    }
}

// ---------------------------------------------------------------------------
// Launch: round(x,sigma) + transpose(sigma) -> fused QKV GEMM -> flash
//         -> out GEMM + bias
// ---------------------------------------------------------------------------
extern "C" void kernel_launch(void* const* d_in, const int* in_sizes, int n_in,
                              void* d_out, int out_size)
{
    const float* x  = (const float*)d_in[0];
    const float* Wq = (const float*)d_in[1];
    const float* Wk = (const float*)d_in[2];
    const float* Wv = (const float*)d_in[3];
    const float* Wo = (const float*)d_in[4];
    const float* bo = (const float*)d_in[5];
    float* out = (float*)d_out;

    float *pq, *pk, *pv, *pc, *pw, *pxr;
    cudaGetSymbolAddress((void**)&pq, g_q);
    cudaGetSymbolAddress((void**)&pk, g_k);
    cudaGetSymbolAddress((void**)&pv, g_v);
    cudaGetSymbolAddress((void**)&pc, g_ctx);
    cudaGetSymbolAddress((void**)&pw, g_wT);
    cudaGetSymbolAddress((void**)&pxr, g_xr);

    round_kernel<<<MTOT * DMODEL / 8 / 256, 256>>>(x, pxr);
    transpose_round4_kernel<<<dim3(DMODEL / 32, DMODEL / 32, 4), dim3(32, 8)>>>(
        Wq, Wk, Wv, Wo, pw);

    cudaFuncSetAttribute(tf32_gemm_kernel<1, 0, 1>,
                         cudaFuncAttributeMaxDynamicSharedMemorySize, GSM_TOTAL);
    cudaFuncSetAttribute(tf32_gemm_kernel<0, 1, 0>,
                         cudaFuncAttributeMaxDynamicSharedMemorySize, GSM_TOTAL);

    tf32_gemm_kernel<1, 0, 1><<<dim3(24, MTOT / 128), 256, GSM_TOTAL>>>(
        pxr, pw, nullptr, pq, pk, pv);

    size_t smem = F_TOTAL * sizeof(float);   // 110,592 B
    cudaFuncSetAttribute(flash_mma_kernel,
                         cudaFuncAttributeMaxDynamicSharedMemorySize, (int)smem);
    flash_mma_kernel<<<dim3(SEQ / 128, BATCH * NHEAD), 256, smem>>>(pq, pk, pv, pc);

    tf32_gemm_kernel<0, 1, 0><<<dim3(8, MTOT / 128), 256, GSM_TOTAL>>>(
        pc, pw + 3 * (size_t)DMODEL * DMODEL, bo, out, nullptr, nullptr);
}